// round 2
// baseline (speedup 1.0000x reference)
#include <cuda_runtime.h>
#include <math.h>

#define Nn 100000
#define Ee 1000000
#define EP (Ee + Nn)      // edges + self loops = 1,100,000
#define FIN 128
#define D1 64             // HEADS*HID
#define H1 4
#define HID 16
#define C2 16
#define SLOPE 0.2f

// ---------------- scratch (static device arrays; no allocation) -------------
__device__ float g_h1[Nn * D1];
__device__ float g_as1[Nn * H1];
__device__ float g_ad1[Nn * H1];
__device__ float g_m1[Nn * H1];
__device__ float g_den1[Nn * H1];
__device__ float g_agg1[Nn * D1];

__device__ float g_h2[Nn * C2];
__device__ float g_as2[Nn];
__device__ float g_ad2[Nn];
__device__ float g_m2[Nn];
__device__ float g_den2[Nn];
__device__ float g_agg2[Nn * C2];

// ---------------- helpers ---------------------------------------------------
__device__ __forceinline__ float lrelu(float v) { return v > 0.f ? v : SLOPE * v; }

// float atomic max via monotone int/uint encoding
__device__ __forceinline__ void atomicMaxF(float* addr, float v) {
    if (v >= 0.f) atomicMax((int*)addr, __float_as_int(v));
    else          atomicMin((unsigned int*)addr, __float_as_uint(v));
}

__device__ __forceinline__ void edge_sd(int i, const int* __restrict__ ei,
                                        int& s, int& d) {
    if (i < Ee) { s = ei[i]; d = ei[i + Ee]; }
    else        { s = d = i - Ee; }
}

// ---------------- init ------------------------------------------------------
__global__ void k_init() {
    int i = blockIdx.x * blockDim.x + threadIdx.x;
    if (i < Nn * D1) g_agg1[i] = 0.f;
    if (i < Nn * C2) g_agg2[i] = 0.f;
    if (i < Nn * H1) { g_m1[i] = -INFINITY; g_den1[i] = 0.f; }
    if (i < Nn)      { g_m2[i] = -INFINITY; g_den2[i] = 0.f; }
}

// ---------------- layer 1: h1 = x @ W1, plus per-head alpha dots ------------
#define NPB1 16
__global__ void k_gemm1(const float* __restrict__ x, const float* __restrict__ W1,
                        const float* __restrict__ a_src1, const float* __restrict__ a_dst1) {
    __shared__ float Ws[FIN * D1];       // 32 KB
    __shared__ float xs[NPB1][FIN];      // 8 KB
    int tid = threadIdx.x;
    int base = blockIdx.x * NPB1;
    for (int i = tid; i < FIN * D1; i += 256) Ws[i] = W1[i];
    for (int i = tid; i < NPB1 * FIN; i += 256) {
        int nl = i >> 7, k = i & 127;
        int n = base + nl;
        xs[nl][k] = (n < Nn) ? x[n * FIN + k] : 0.f;
    }
    __syncthreads();

    int j   = tid & 63;      // output feature
    int sub = tid >> 6;      // 0..3, constant within a warp
    float asj = a_src1[j];
    float adj = a_dst1[j];
    #pragma unroll
    for (int it = 0; it < NPB1 / 4; ++it) {
        int nl = sub + it * 4;
        int n = base + nl;
        float acc = 0.f;
        #pragma unroll 16
        for (int k = 0; k < FIN; ++k) acc += xs[nl][k] * Ws[k * D1 + j];
        float sc = acc * asj;
        float dc = acc * adj;
        #pragma unroll
        for (int off = 8; off > 0; off >>= 1) {
            sc += __shfl_xor_sync(0xffffffffu, sc, off);
            dc += __shfl_xor_sync(0xffffffffu, dc, off);
        }
        if (n < Nn) {
            g_h1[n * D1 + j] = acc;
            if ((j & 15) == 0) {
                int hh = j >> 4;
                g_as1[n * H1 + hh] = sc;
                g_ad1[n * H1 + hh] = dc;
            }
        }
    }
}

// ---------------- layer 1 edge passes ---------------------------------------
__global__ void k_max1(const int* __restrict__ ei) {
    int i = blockIdx.x * blockDim.x + threadIdx.x;
    if (i >= EP) return;
    int s, d; edge_sd(i, ei, s, d);
    float4 as = *(const float4*)&g_as1[s * 4];
    float4 ad = *(const float4*)&g_ad1[d * 4];
    atomicMaxF(&g_m1[d * 4 + 0], lrelu(as.x + ad.x));
    atomicMaxF(&g_m1[d * 4 + 1], lrelu(as.y + ad.y));
    atomicMaxF(&g_m1[d * 4 + 2], lrelu(as.z + ad.z));
    atomicMaxF(&g_m1[d * 4 + 3], lrelu(as.w + ad.w));
}

__global__ void k_den1(const int* __restrict__ ei) {
    int i = blockIdx.x * blockDim.x + threadIdx.x;
    if (i >= EP) return;
    int s, d; edge_sd(i, ei, s, d);
    float4 as = *(const float4*)&g_as1[s * 4];
    float4 ad = *(const float4*)&g_ad1[d * 4];
    float4 m  = *(const float4*)&g_m1[d * 4];
    atomicAdd(&g_den1[d * 4 + 0], expf(lrelu(as.x + ad.x) - m.x));
    atomicAdd(&g_den1[d * 4 + 1], expf(lrelu(as.y + ad.y) - m.y));
    atomicAdd(&g_den1[d * 4 + 2], expf(lrelu(as.z + ad.z) - m.z));
    atomicAdd(&g_den1[d * 4 + 3], expf(lrelu(as.w + ad.w) - m.w));
}

// warp per edge: 64 features scattered with per-head softmax weight
__global__ void k_msg1(const int* __restrict__ ei) {
    int t = blockIdx.x * blockDim.x + threadIdx.x;
    int e = t >> 5, lane = t & 31;
    if (e >= EP) return;
    int s, d; edge_sd(e, ei, s, d);
    float w = 0.f;
    if (lane < 4) {
        float a = lrelu(g_as1[s * 4 + lane] + g_ad1[d * 4 + lane]);
        w = expf(a - g_m1[d * 4 + lane]) / (g_den1[d * 4 + lane] + 1e-16f);
    }
    float w_lo = __shfl_sync(0xffffffffu, w, lane >> 4);
    float w_hi = __shfl_sync(0xffffffffu, w, (lane >> 4) + 2);
    float h_lo = g_h1[s * D1 + lane];
    float h_hi = g_h1[s * D1 + lane + 32];
    atomicAdd(&g_agg1[d * D1 + lane],      h_lo * w_lo);
    atomicAdd(&g_agg1[d * D1 + lane + 32], h_hi * w_hi);
}

// ---------------- layer 2: h2 = elu(agg1 + b1) @ W2, plus alpha dots --------
__global__ void k_gemm2(const float* __restrict__ W2, const float* __restrict__ b1,
                        const float* __restrict__ a_src2, const float* __restrict__ a_dst2) {
    __shared__ float Ws[D1 * C2];
    __shared__ float hs[16][D1 + 1];
    int tid = threadIdx.x;
    int base = blockIdx.x * 16;
    for (int i = tid; i < D1 * C2; i += 256) Ws[i] = W2[i];
    for (int i = tid; i < 16 * D1; i += 256) {
        int nl = i >> 6, k = i & 63;
        int n = base + nl;
        float v = 0.f;
        if (n < Nn) v = g_agg1[n * D1 + k] + b1[k];
        hs[nl][k] = v > 0.f ? v : (expf(v) - 1.f);   // ELU
    }
    __syncthreads();
    int nl = tid >> 4, c = tid & 15;
    int n = base + nl;
    float acc = 0.f;
    #pragma unroll
    for (int k = 0; k < D1; ++k) acc += hs[nl][k] * Ws[k * C2 + c];
    float sc = acc * a_src2[c];
    float dc = acc * a_dst2[c];
    #pragma unroll
    for (int off = 8; off > 0; off >>= 1) {
        sc += __shfl_xor_sync(0xffffffffu, sc, off);
        dc += __shfl_xor_sync(0xffffffffu, dc, off);
    }
    if (n < Nn) {
        g_h2[n * C2 + c] = acc;
        if (c == 0) { g_as2[n] = sc; g_ad2[n] = dc; }
    }
}

// ---------------- layer 2 edge passes ---------------------------------------
__global__ void k_max2(const int* __restrict__ ei) {
    int i = blockIdx.x * blockDim.x + threadIdx.x;
    if (i >= EP) return;
    int s, d; edge_sd(i, ei, s, d);
    atomicMaxF(&g_m2[d], lrelu(g_as2[s] + g_ad2[d]));
}

__global__ void k_den2(const int* __restrict__ ei) {
    int i = blockIdx.x * blockDim.x + threadIdx.x;
    if (i >= EP) return;
    int s, d; edge_sd(i, ei, s, d);
    atomicAdd(&g_den2[d], expf(lrelu(g_as2[s] + g_ad2[d]) - g_m2[d]));
}

__global__ void k_msg2(const int* __restrict__ ei) {
    int t = blockIdx.x * blockDim.x + threadIdx.x;
    int e = t >> 4, f = t & 15;
    if (e >= EP) return;
    int s, d; edge_sd(e, ei, s, d);
    float w = expf(lrelu(g_as2[s] + g_ad2[d]) - g_m2[d]) / (g_den2[d] + 1e-16f);
    atomicAdd(&g_agg2[d * C2 + f], g_h2[s * C2 + f] * w);
}

// ---------------- finalize ---------------------------------------------------
__global__ void k_fin(float* __restrict__ out, const float* __restrict__ b2) {
    int i = blockIdx.x * blockDim.x + threadIdx.x;
    if (i < Nn * C2) out[i] = g_agg2[i] + b2[i & 15];
}

// ---------------- launch ------------------------------------------------------
extern "C" void kernel_launch(void* const* d_in, const int* in_sizes, int n_in,
                              void* d_out, int out_size) {
    const float* x       = (const float*)d_in[0];
    const int*   ei      = (const int*)d_in[1];   // JAX default: int64 request -> int32
    const float* W1      = (const float*)d_in[2];
    const float* a_src1  = (const float*)d_in[3];
    const float* a_dst1  = (const float*)d_in[4];
    const float* b1      = (const float*)d_in[5];
    const float* W2      = (const float*)d_in[6];
    const float* a_src2  = (const float*)d_in[7];
    const float* a_dst2  = (const float*)d_in[8];
    const float* b2      = (const float*)d_in[9];
    float* out = (float*)d_out;

    k_init<<<(Nn * D1 + 255) / 256, 256>>>();
    k_gemm1<<<(Nn + NPB1 - 1) / NPB1, 256>>>(x, W1, a_src1, a_dst1);
    k_max1<<<(EP + 255) / 256, 256>>>(ei);
    k_den1<<<(EP + 255) / 256, 256>>>(ei);
    k_msg1<<<(EP * 32 + 255) / 256, 256>>>(ei);
    k_gemm2<<<(Nn + 15) / 16, 256>>>(W2, b1, a_src2, a_dst2);
    k_max2<<<(EP + 255) / 256, 256>>>(ei);
    k_den2<<<(EP + 255) / 256, 256>>>(ei);
    k_msg2<<<(EP * 16 + 255) / 256, 256>>>(ei);
    k_fin<<<(Nn * C2 + 255) / 256, 256>>>(out, b2);
}

// round 3
// speedup vs baseline: 1.2117x; 1.2117x over previous
#include <cuda_runtime.h>
#include <math.h>

#define Nn 100000
#define Ee 1000000
#define EP (Ee + Nn)      // edges + self loops = 1,100,000
#define FIN 128
#define D1 64             // HEADS*HID
#define H1 4
#define C2 16
#define SLOPE 0.2f

// ---------------- scratch (static device arrays; no allocation) -------------
__device__ float g_h1[Nn * D1];
__device__ float g_as1[Nn * H1];
__device__ float g_ad1[Nn * H1];
__device__ float g_den1[Nn * H1];
__device__ float g_agg1[Nn * D1];

__device__ float g_h2[Nn * C2];
__device__ float g_as2[Nn];
__device__ float g_ad2[Nn];
__device__ float g_den2[Nn];
__device__ float g_agg2[Nn * C2];

// ---------------- helpers ---------------------------------------------------
__device__ __forceinline__ float lrelu(float v) { return v > 0.f ? v : SLOPE * v; }

__device__ __forceinline__ void edge_sd(int i, const int* __restrict__ ei,
                                        int& s, int& d) {
    if (i < Ee) { s = ei[i]; d = ei[i + Ee]; }
    else        { s = d = i - Ee; }
}

// ---------------- init ------------------------------------------------------
__global__ void k_init() {
    int i = blockIdx.x * blockDim.x + threadIdx.x;
    if (i < Nn * D1) g_agg1[i] = 0.f;
    if (i < Nn * C2) g_agg2[i] = 0.f;
    if (i < Nn * H1) g_den1[i] = 0.f;
    if (i < Nn)      g_den2[i] = 0.f;
}

// ---------------- layer 1: h1 = x @ W1, plus per-head alpha dots ------------
#define NPB1 16
__global__ void k_gemm1(const float* __restrict__ x, const float* __restrict__ W1,
                        const float* __restrict__ a_src1, const float* __restrict__ a_dst1) {
    __shared__ float Ws[FIN * D1];       // 32 KB
    __shared__ float xs[NPB1][FIN];      // 8 KB
    int tid = threadIdx.x;
    int base = blockIdx.x * NPB1;
    for (int i = tid; i < FIN * D1; i += 256) Ws[i] = W1[i];
    for (int i = tid; i < NPB1 * FIN; i += 256) {
        int nl = i >> 7, k = i & 127;
        int n = base + nl;
        xs[nl][k] = (n < Nn) ? x[n * FIN + k] : 0.f;
    }
    __syncthreads();

    int j   = tid & 63;      // output feature
    int sub = tid >> 6;      // 0..3, constant within a warp
    float asj = a_src1[j];
    float adj = a_dst1[j];
    #pragma unroll
    for (int it = 0; it < NPB1 / 4; ++it) {
        int nl = sub + it * 4;
        int n = base + nl;
        float acc = 0.f;
        #pragma unroll 16
        for (int k = 0; k < FIN; ++k) acc += xs[nl][k] * Ws[k * D1 + j];
        float sc = acc * asj;
        float dc = acc * adj;
        #pragma unroll
        for (int off = 8; off > 0; off >>= 1) {
            sc += __shfl_xor_sync(0xffffffffu, sc, off);
            dc += __shfl_xor_sync(0xffffffffu, dc, off);
        }
        if (n < Nn) {
            g_h1[n * D1 + j] = acc;
            if ((j & 15) == 0) {
                int hh = j >> 4;
                g_as1[n * H1 + hh] = sc;
                g_ad1[n * H1 + hh] = dc;
            }
        }
    }
}

// ---------------- layer 1: single fused edge pass ----------------------------
// warp per edge: scatter exp-weighted features AND denominator in one pass.
__global__ void k_edge1(const int* __restrict__ ei) {
    int t = blockIdx.x * blockDim.x + threadIdx.x;
    int e = t >> 5, lane = t & 31;
    if (e >= EP) return;
    int s, d; edge_sd(e, ei, s, d);
    float ex = 0.f;
    if (lane < H1)
        ex = expf(lrelu(g_as1[s * H1 + lane] + g_ad1[d * H1 + lane]));
    // feature lane -> head lane>>4 (0/1), lane+32 -> head 2/3
    float w_lo = __shfl_sync(0xffffffffu, ex, lane >> 4);
    float w_hi = __shfl_sync(0xffffffffu, ex, (lane >> 4) + 2);
    float h_lo = g_h1[s * D1 + lane];
    float h_hi = g_h1[s * D1 + lane + 32];
    atomicAdd(&g_agg1[d * D1 + lane],      h_lo * w_lo);
    atomicAdd(&g_agg1[d * D1 + lane + 32], h_hi * w_hi);
    if (lane < H1) atomicAdd(&g_den1[d * H1 + lane], ex);
}

// ---------------- layer 2: h2 = elu(agg1/den1 + b1) @ W2, plus alpha dots ----
__global__ void k_gemm2(const float* __restrict__ W2, const float* __restrict__ b1,
                        const float* __restrict__ a_src2, const float* __restrict__ a_dst2) {
    __shared__ float Ws[D1 * C2];
    __shared__ float hs[16][D1 + 1];
    int tid = threadIdx.x;
    int base = blockIdx.x * 16;
    for (int i = tid; i < D1 * C2; i += 256) Ws[i] = W2[i];
    for (int i = tid; i < 16 * D1; i += 256) {
        int nl = i >> 6, k = i & 63;
        int n = base + nl;
        float v = 0.f;
        if (n < Nn) {
            float den = g_den1[n * H1 + (k >> 4)] + 1e-16f;
            v = g_agg1[n * D1 + k] / den + b1[k];
        }
        hs[nl][k] = v > 0.f ? v : (expf(v) - 1.f);   // ELU
    }
    __syncthreads();
    int nl = tid >> 4, c = tid & 15;
    int n = base + nl;
    float acc = 0.f;
    #pragma unroll
    for (int k = 0; k < D1; ++k) acc += hs[nl][k] * Ws[k * C2 + c];
    float sc = acc * a_src2[c];
    float dc = acc * a_dst2[c];
    #pragma unroll
    for (int off = 8; off > 0; off >>= 1) {
        sc += __shfl_xor_sync(0xffffffffu, sc, off);
        dc += __shfl_xor_sync(0xffffffffu, dc, off);
    }
    if (n < Nn) {
        g_h2[n * C2 + c] = acc;
        if (c == 0) { g_as2[n] = sc; g_ad2[n] = dc; }
    }
}

// ---------------- layer 2: single fused edge pass ----------------------------
// 4 threads per edge: each does a float4 worth of scalar atomics.
__global__ void k_edge2(const int* __restrict__ ei) {
    int t = blockIdx.x * blockDim.x + threadIdx.x;
    int e = t >> 2, sub = t & 3;
    if (e >= EP) return;
    int s, d; edge_sd(e, ei, s, d);
    float ex = expf(lrelu(g_as2[s] + g_ad2[d]));
    float4 h = *(const float4*)&g_h2[s * C2 + sub * 4];
    float* base = &g_agg2[d * C2 + sub * 4];
    atomicAdd(base + 0, h.x * ex);
    atomicAdd(base + 1, h.y * ex);
    atomicAdd(base + 2, h.z * ex);
    atomicAdd(base + 3, h.w * ex);
    if (sub == 0) atomicAdd(&g_den2[d], ex);
}

// ---------------- finalize ----------------------------------------------------
__global__ void k_fin(float* __restrict__ out, const float* __restrict__ b2) {
    int i = blockIdx.x * blockDim.x + threadIdx.x;
    if (i < Nn * C2) {
        float den = g_den2[i >> 4] + 1e-16f;
        out[i] = g_agg2[i] / den + b2[i & 15];
    }
}

// ---------------- launch ------------------------------------------------------
extern "C" void kernel_launch(void* const* d_in, const int* in_sizes, int n_in,
                              void* d_out, int out_size) {
    const float* x       = (const float*)d_in[0];
    const int*   ei      = (const int*)d_in[1];   // int32 (JAX x64 disabled)
    const float* W1      = (const float*)d_in[2];
    const float* a_src1  = (const float*)d_in[3];
    const float* a_dst1  = (const float*)d_in[4];
    const float* b1      = (const float*)d_in[5];
    const float* W2      = (const float*)d_in[6];
    const float* a_src2  = (const float*)d_in[7];
    const float* a_dst2  = (const float*)d_in[8];
    const float* b2      = (const float*)d_in[9];
    float* out = (float*)d_out;

    k_init<<<(Nn * D1 + 255) / 256, 256>>>();
    k_gemm1<<<(Nn + NPB1 - 1) / NPB1, 256>>>(x, W1, a_src1, a_dst1);
    k_edge1<<<(EP * 32 + 255) / 256, 256>>>(ei);
    k_gemm2<<<(Nn + 15) / 16, 256>>>(W2, b1, a_src2, a_dst2);
    k_edge2<<<(EP * 4 + 255) / 256, 256>>>(ei);
    k_fin<<<(Nn * C2 + 255) / 256, 256>>>(out, b2);
}

// round 4
// speedup vs baseline: 1.4862x; 1.2265x over previous
#include <cuda_runtime.h>
#include <math.h>

#define Nn 100000
#define Ee 1000000
#define EP (Ee + Nn)      // 1,100,000
#define FIN 128
#define D1 64             // HEADS*HID
#define H1 4
#define C2 16
#define SLOPE 0.2f

// ---------------- scratch (static device arrays; no allocation) -------------
__device__ __align__(16) float g_h1[Nn * D1];
__device__ __align__(16) float g_as1[Nn * H1];
__device__ __align__(16) float g_ad1[Nn * H1];
__device__ __align__(16) float g_den1[Nn * H1];
__device__ __align__(16) float g_agg1[Nn * D1];

__device__ __align__(16) float g_h2[Nn * C2];
__device__ __align__(16) float g_as2[Nn];
__device__ __align__(16) float g_ad2[Nn];
__device__ __align__(16) float g_den2[Nn];
__device__ __align__(16) float g_agg2[Nn * C2];

// ---------------- helpers ---------------------------------------------------
__device__ __forceinline__ float lrelu(float v) { return v > 0.f ? v : SLOPE * v; }

__device__ __forceinline__ void red4(float* p, float a, float b, float c, float d) {
    asm volatile("red.global.add.v4.f32 [%0], {%1,%2,%3,%4};"
                 :: "l"(p), "f"(a), "f"(b), "f"(c), "f"(d) : "memory");
}

__device__ __forceinline__ void edge_sd(int i, const int* __restrict__ ei,
                                        int& s, int& d) {
    if (i < Ee) { s = ei[i]; d = ei[i + Ee]; }
    else        { s = d = i - Ee; }
}

// ---------------- init (vectorized zeroing) ----------------------------------
__global__ void k_init() {
    int i = blockIdx.x * blockDim.x + threadIdx.x;
    float4 z = make_float4(0.f, 0.f, 0.f, 0.f);
    if (i < Nn * D1 / 4) ((float4*)g_agg1)[i] = z;
    if (i < Nn * C2 / 4) ((float4*)g_agg2)[i] = z;
    if (i < Nn * H1 / 4) ((float4*)g_den1)[i] = z;
    if (i < Nn / 4)      ((float4*)g_den2)[i] = z;
}

// ---------------- layer 1 GEMM: 32 nodes/block, 8 outputs/thread ------------
#define NPB1 32
__global__ void k_gemm1(const float* __restrict__ x, const float* __restrict__ W1,
                        const float* __restrict__ a_src1, const float* __restrict__ a_dst1) {
    __shared__ float Ws[FIN * D1];        // 32 KB  [k][j]
    __shared__ float xs[NPB1][FIN];       // 16 KB
    int tid = threadIdx.x;
    int base = blockIdx.x * NPB1;
    for (int i = tid; i < FIN * D1 / 4; i += 256)
        ((float4*)Ws)[i] = ((const float4*)W1)[i];
    for (int i = tid; i < NPB1 * FIN / 4; i += 256) {
        int nl = i >> 5, k4 = i & 31;
        int n = base + nl;
        float4 v = make_float4(0.f, 0.f, 0.f, 0.f);
        if (n < Nn) v = ((const float4*)(x + (size_t)n * FIN))[k4];
        ((float4*)&xs[nl][0])[k4] = v;
    }
    __syncthreads();

    int nl = tid >> 3, jo = tid & 7;      // j = jo*8 .. jo*8+7
    int n = base + nl;
    float acc[8] = {0.f, 0.f, 0.f, 0.f, 0.f, 0.f, 0.f, 0.f};
    #pragma unroll 8
    for (int k = 0; k < FIN; ++k) {
        float xv = xs[nl][k];
        float4 w0 = *(const float4*)&Ws[k * D1 + jo * 8];
        float4 w1 = *(const float4*)&Ws[k * D1 + jo * 8 + 4];
        acc[0] += xv * w0.x; acc[1] += xv * w0.y; acc[2] += xv * w0.z; acc[3] += xv * w0.w;
        acc[4] += xv * w1.x; acc[5] += xv * w1.y; acc[6] += xv * w1.z; acc[7] += xv * w1.w;
    }
    float sc = 0.f, dc = 0.f;
    #pragma unroll
    for (int m = 0; m < 8; ++m) {
        sc += acc[m] * a_src1[jo * 8 + m];
        dc += acc[m] * a_dst1[jo * 8 + m];
    }
    // jo and jo^1 belong to the same head (head = jo>>1)
    sc += __shfl_xor_sync(0xffffffffu, sc, 1);
    dc += __shfl_xor_sync(0xffffffffu, dc, 1);
    if (n < Nn) {
        *(float4*)&g_h1[n * D1 + jo * 8]     = make_float4(acc[0], acc[1], acc[2], acc[3]);
        *(float4*)&g_h1[n * D1 + jo * 8 + 4] = make_float4(acc[4], acc[5], acc[6], acc[7]);
        if (!(jo & 1)) {
            int hh = jo >> 1;
            g_as1[n * H1 + hh] = sc;
            g_ad1[n * H1 + hh] = dc;
        }
    }
}

// ---------------- layer 1 fused edge pass: 16 threads/edge, v4 atomics ------
__global__ void k_edge1(const int* __restrict__ ei) {
    int t = blockIdx.x * blockDim.x + threadIdx.x;   // grid exact: EP*16 threads
    int e = t >> 4, l = t & 15;
    int s, d; edge_sd(e, ei, s, d);
    int lane = threadIdx.x & 31;
    int grp  = lane & 16;
    float ex = 0.f;
    if (l < H1)
        ex = expf(lrelu(g_as1[s * H1 + l] + g_ad1[d * H1 + l]));
    // feature quad l covers floats 4l..4l+3 -> head l>>2
    float w = __shfl_sync(0xffffffffu, ex, grp + (l >> 2));
    float4 h = *(const float4*)&g_h1[s * D1 + l * 4];
    red4(&g_agg1[d * D1 + l * 4], h.x * w, h.y * w, h.z * w, h.w * w);
    float e1 = __shfl_sync(0xffffffffu, ex, grp + 1);
    float e2 = __shfl_sync(0xffffffffu, ex, grp + 2);
    float e3 = __shfl_sync(0xffffffffu, ex, grp + 3);
    if (l == 0) red4(&g_den1[d * H1], ex, e1, e2, e3);
}

// ---------------- layer 2 GEMM: 64 nodes/block, 4 outputs/thread ------------
__global__ void k_gemm2(const float* __restrict__ W2, const float* __restrict__ b1,
                        const float* __restrict__ a_src2, const float* __restrict__ a_dst2) {
    __shared__ float Ws[D1 * C2];          // 4 KB  [k][c]
    __shared__ float hs[64][D1 + 1];       // ~16.6 KB
    int tid = threadIdx.x;
    int base = blockIdx.x * 64;
    for (int i = tid; i < D1 * C2; i += 256) Ws[i] = W2[i];
    for (int i = tid; i < 64 * D1; i += 256) {
        int nl = i >> 6, k = i & 63;
        int n = base + nl;
        float v = 0.f;
        if (n < Nn) {
            float den = g_den1[n * H1 + (k >> 4)] + 1e-16f;
            v = g_agg1[n * D1 + k] / den + b1[k];
        }
        hs[nl][k] = v > 0.f ? v : (expf(v) - 1.f);   // ELU
    }
    __syncthreads();

    int nl = tid >> 2, cq = tid & 3;       // c = cq*4 .. cq*4+3
    int n = base + nl;
    float4 acc = make_float4(0.f, 0.f, 0.f, 0.f);
    #pragma unroll 16
    for (int k = 0; k < D1; ++k) {
        float hv = hs[nl][k];
        float4 w = *(const float4*)&Ws[k * C2 + cq * 4];
        acc.x += hv * w.x; acc.y += hv * w.y; acc.z += hv * w.z; acc.w += hv * w.w;
    }
    float sc = acc.x * a_src2[cq * 4] + acc.y * a_src2[cq * 4 + 1]
             + acc.z * a_src2[cq * 4 + 2] + acc.w * a_src2[cq * 4 + 3];
    float dc = acc.x * a_dst2[cq * 4] + acc.y * a_dst2[cq * 4 + 1]
             + acc.z * a_dst2[cq * 4 + 2] + acc.w * a_dst2[cq * 4 + 3];
    sc += __shfl_xor_sync(0xffffffffu, sc, 1);
    sc += __shfl_xor_sync(0xffffffffu, sc, 2);
    dc += __shfl_xor_sync(0xffffffffu, dc, 1);
    dc += __shfl_xor_sync(0xffffffffu, dc, 2);
    if (n < Nn) {
        *(float4*)&g_h2[n * C2 + cq * 4] = acc;
        if (cq == 0) { g_as2[n] = sc; g_ad2[n] = dc; }
    }
}

// ---------------- layer 2 fused edge pass: 4 threads/edge, v4 atomics -------
__global__ void k_edge2(const int* __restrict__ ei) {
    int t = blockIdx.x * blockDim.x + threadIdx.x;
    int e = t >> 2, sub = t & 3;
    if (e >= EP) return;
    int s, d; edge_sd(e, ei, s, d);
    float ex = expf(lrelu(g_as2[s] + g_ad2[d]));
    float4 h = *(const float4*)&g_h2[s * C2 + sub * 4];
    red4(&g_agg2[d * C2 + sub * 4], h.x * ex, h.y * ex, h.z * ex, h.w * ex);
    if (sub == 0) atomicAdd(&g_den2[d], ex);
}

// ---------------- finalize ----------------------------------------------------
__global__ void k_fin(float* __restrict__ out, const float* __restrict__ b2) {
    int i = blockIdx.x * blockDim.x + threadIdx.x;
    if (i < Nn * C2 / 4) {
        int node = i >> 2, cb = (i & 3) * 4;
        float den = g_den2[node] + 1e-16f;
        float4 a = ((const float4*)g_agg2)[i];
        float4 o;
        o.x = a.x / den + b2[cb];
        o.y = a.y / den + b2[cb + 1];
        o.z = a.z / den + b2[cb + 2];
        o.w = a.w / den + b2[cb + 3];
        ((float4*)out)[i] = o;
    }
}

// ---------------- launch ------------------------------------------------------
extern "C" void kernel_launch(void* const* d_in, const int* in_sizes, int n_in,
                              void* d_out, int out_size) {
    const float* x       = (const float*)d_in[0];
    const int*   ei      = (const int*)d_in[1];   // int32 (JAX x64 disabled)
    const float* W1      = (const float*)d_in[2];
    const float* a_src1  = (const float*)d_in[3];
    const float* a_dst1  = (const float*)d_in[4];
    const float* b1      = (const float*)d_in[5];
    const float* W2      = (const float*)d_in[6];
    const float* a_src2  = (const float*)d_in[7];
    const float* a_dst2  = (const float*)d_in[8];
    const float* b2      = (const float*)d_in[9];
    float* out = (float*)d_out;

    k_init <<<(Nn * D1 / 4 + 255) / 256, 256>>>();
    k_gemm1<<<(Nn + NPB1 - 1) / NPB1, 256>>>(x, W1, a_src1, a_dst1);
    k_edge1<<<(EP * 16 + 255) / 256, 256>>>(ei);
    k_gemm2<<<(Nn + 63) / 64, 256>>>(W2, b1, a_src2, a_dst2);
    k_edge2<<<(EP * 4 + 255) / 256, 256>>>(ei);
    k_fin  <<<(Nn * C2 / 4 + 255) / 256, 256>>>(out, b2);
}

// round 7
// speedup vs baseline: 1.5277x; 1.0280x over previous
#include <cuda_runtime.h>
#include <math.h>

#define Nn 100000
#define Ee 1000000
#define EP (Ee + Nn)      // 1,100,000
#define FIN 128
#define D1 64             // HEADS*HID
#define H1 4
#define C2 16
#define SLOPE 0.2f

// ---------------- scratch (static device arrays; no allocation) -------------
__device__ __align__(16) float g_h1[Nn * D1];
__device__ __align__(16) float g_as1[Nn * H1];
__device__ __align__(16) float g_ad1[Nn * H1];
__device__ __align__(16) float g_den1[Nn * H1];
__device__ __align__(16) float g_agg1[Nn * D1];

__device__ __align__(16) float g_h2[Nn * C2];
__device__ __align__(16) float g_as2[Nn];
__device__ __align__(16) float g_ad2[Nn];
__device__ __align__(16) float g_den2[Nn];
__device__ __align__(16) float g_agg2[Nn * C2];

// ---------------- helpers ---------------------------------------------------
__device__ __forceinline__ float lrelu(float v) { return v > 0.f ? v : SLOPE * v; }

__device__ __forceinline__ void red4(float* p, float a, float b, float c, float d) {
    asm volatile("red.global.add.v4.f32 [%0], {%1,%2,%3,%4};"
                 :: "l"(p), "f"(a), "f"(b), "f"(c), "f"(d) : "memory");
}

__device__ __forceinline__ void edge_sd(int i, const int* __restrict__ ei,
                                        int& s, int& d) {
    if (i < Ee) { s = ei[i]; d = ei[i + Ee]; }
    else        { s = d = i - Ee; }
}

// ---------------- init (vectorized zeroing) ----------------------------------
__global__ void k_init() {
    int i = blockIdx.x * blockDim.x + threadIdx.x;
    float4 z = make_float4(0.f, 0.f, 0.f, 0.f);
    if (i < Nn * D1 / 4) ((float4*)g_agg1)[i] = z;
    if (i < Nn * C2 / 4) ((float4*)g_agg2)[i] = z;
    if (i < Nn * H1 / 4) ((float4*)g_den1)[i] = z;
    if (i < Nn / 4)      ((float4*)g_den2)[i] = z;
}

// ---------------- layer 1 GEMM: 32 nodes/block, 8 outputs/thread ------------
// xs rows XOR-swizzled in float4 units: group g of node nl stored at g^(nl&3).
// Within a warp (4 distinct nl, 8 threads each) every k4 step hits 4 disjoint
// bank quads -> conflict-free without padding (smem stays at exactly 48 KB).
#define NPB1 32
__global__ void k_gemm1(const float* __restrict__ x, const float* __restrict__ W1,
                        const float* __restrict__ a_src1, const float* __restrict__ a_dst1) {
    __shared__ float Ws[FIN * D1];        // 32 KB  [k][j]
    __shared__ float xs[NPB1][FIN];       // 16 KB, swizzled
    int tid = threadIdx.x;
    int base = blockIdx.x * NPB1;
    for (int i = tid; i < FIN * D1 / 4; i += 256)
        ((float4*)Ws)[i] = ((const float4*)W1)[i];
    for (int i = tid; i < NPB1 * FIN / 4; i += 256) {
        int nl = i >> 5, k4 = i & 31;
        int n = base + nl;
        float4 v = make_float4(0.f, 0.f, 0.f, 0.f);
        if (n < Nn) v = ((const float4*)(x + (size_t)n * FIN))[k4];
        ((float4*)&xs[nl][0])[k4 ^ (nl & 3)] = v;
    }
    __syncthreads();

    int nl = tid >> 3, jo = tid & 7;      // j = jo*8 .. jo*8+7
    int n = base + nl;
    int sw = nl & 3;
    const float4* xr = (const float4*)&xs[nl][0];
    float acc[8] = {0.f, 0.f, 0.f, 0.f, 0.f, 0.f, 0.f, 0.f};
    #pragma unroll 4
    for (int k4 = 0; k4 < FIN / 4; ++k4) {
        float4 xq = xr[k4 ^ sw];
        int kb = k4 * 4;
        #pragma unroll
        for (int kk = 0; kk < 4; ++kk) {
            float xv = kk == 0 ? xq.x : kk == 1 ? xq.y : kk == 2 ? xq.z : xq.w;
            float4 w0 = *(const float4*)&Ws[(kb + kk) * D1 + jo * 8];
            float4 w1 = *(const float4*)&Ws[(kb + kk) * D1 + jo * 8 + 4];
            acc[0] += xv * w0.x; acc[1] += xv * w0.y; acc[2] += xv * w0.z; acc[3] += xv * w0.w;
            acc[4] += xv * w1.x; acc[5] += xv * w1.y; acc[6] += xv * w1.z; acc[7] += xv * w1.w;
        }
    }
    float sc = 0.f, dc = 0.f;
    #pragma unroll
    for (int m = 0; m < 8; ++m) {
        sc += acc[m] * a_src1[jo * 8 + m];
        dc += acc[m] * a_dst1[jo * 8 + m];
    }
    // jo and jo^1 belong to the same head (head = jo>>1)
    sc += __shfl_xor_sync(0xffffffffu, sc, 1);
    dc += __shfl_xor_sync(0xffffffffu, dc, 1);
    if (n < Nn) {
        *(float4*)&g_h1[n * D1 + jo * 8]     = make_float4(acc[0], acc[1], acc[2], acc[3]);
        *(float4*)&g_h1[n * D1 + jo * 8 + 4] = make_float4(acc[4], acc[5], acc[6], acc[7]);
        if (!(jo & 1)) {
            int hh = jo >> 1;
            g_as1[n * H1 + hh] = sc;
            g_ad1[n * H1 + hh] = dc;
        }
    }
}

// ---------------- layer 1 fused edge pass: 16 threads/edge, v4 atomics ------
__global__ void k_edge1(const int* __restrict__ ei) {
    int t = blockIdx.x * blockDim.x + threadIdx.x;   // grid exact: EP*16 threads
    int e = t >> 4, l = t & 15;
    int s, d; edge_sd(e, ei, s, d);
    int lane = threadIdx.x & 31;
    int grp  = lane & 16;
    float ex = 0.f;
    if (l < H1)
        ex = __expf(lrelu(g_as1[s * H1 + l] + g_ad1[d * H1 + l]));
    // feature quad l covers floats 4l..4l+3 -> head l>>2
    float w = __shfl_sync(0xffffffffu, ex, grp + (l >> 2));
    float4 h = *(const float4*)&g_h1[s * D1 + l * 4];
    red4(&g_agg1[d * D1 + l * 4], h.x * w, h.y * w, h.z * w, h.w * w);
    float e1 = __shfl_sync(0xffffffffu, ex, grp + 1);
    float e2 = __shfl_sync(0xffffffffu, ex, grp + 2);
    float e3 = __shfl_sync(0xffffffffu, ex, grp + 3);
    if (l == 0) red4(&g_den1[d * H1], ex, e1, e2, e3);
}

// ---------------- layer 2 GEMM: 64 nodes/block, 4 outputs/thread ------------
__global__ void k_gemm2(const float* __restrict__ W2, const float* __restrict__ b1,
                        const float* __restrict__ a_src2, const float* __restrict__ a_dst2) {
    __shared__ float Ws[D1 * C2];          // 4 KB  [k][c]
    __shared__ float hs[64][D1 + 1];       // ~16.6 KB
    __shared__ float invd[256];            // per-(node,head) reciprocal denominators
    int tid = threadIdx.x;
    int base = blockIdx.x * 64;
    for (int i = tid; i < D1 * C2; i += 256) Ws[i] = W2[i];
    {
        int n = base + (tid >> 2);
        float den = (n < Nn) ? g_den1[n * H1 + (tid & 3)] : 1.f;
        invd[tid] = __frcp_rn(den + 1e-16f);
    }
    __syncthreads();
    for (int i = tid; i < 64 * D1; i += 256) {
        int nl = i >> 6, k = i & 63;
        int n = base + nl;
        float v = 0.f;
        if (n < Nn)
            v = g_agg1[n * D1 + k] * invd[nl * 4 + (k >> 4)] + b1[k];
        hs[nl][k] = v > 0.f ? v : (__expf(v) - 1.f);   // ELU
    }
    __syncthreads();

    int nl = tid >> 2, cq = tid & 3;       // c = cq*4 .. cq*4+3
    int n = base + nl;
    float4 acc = make_float4(0.f, 0.f, 0.f, 0.f);
    #pragma unroll 16
    for (int k = 0; k < D1; ++k) {
        float hv = hs[nl][k];
        float4 w = *(const float4*)&Ws[k * C2 + cq * 4];
        acc.x += hv * w.x; acc.y += hv * w.y; acc.z += hv * w.z; acc.w += hv * w.w;
    }
    float sc = acc.x * a_src2[cq * 4] + acc.y * a_src2[cq * 4 + 1]
             + acc.z * a_src2[cq * 4 + 2] + acc.w * a_src2[cq * 4 + 3];
    float dc = acc.x * a_dst2[cq * 4] + acc.y * a_dst2[cq * 4 + 1]
             + acc.z * a_dst2[cq * 4 + 2] + acc.w * a_dst2[cq * 4 + 3];
    sc += __shfl_xor_sync(0xffffffffu, sc, 1);
    sc += __shfl_xor_sync(0xffffffffu, sc, 2);
    dc += __shfl_xor_sync(0xffffffffu, dc, 1);
    dc += __shfl_xor_sync(0xffffffffu, dc, 2);
    if (n < Nn) {
        *(float4*)&g_h2[n * C2 + cq * 4] = acc;
        if (cq == 0) { g_as2[n] = sc; g_ad2[n] = dc; }
    }
}

// ---------------- layer 2 fused edge pass: 4 threads/edge, v4 atomics -------
__global__ void k_edge2(const int* __restrict__ ei) {
    int t = blockIdx.x * blockDim.x + threadIdx.x;
    int e = t >> 2, sub = t & 3;
    if (e >= EP) return;
    int s, d; edge_sd(e, ei, s, d);
    float ex = __expf(lrelu(g_as2[s] + g_ad2[d]));
    float4 h = *(const float4*)&g_h2[s * C2 + sub * 4];
    red4(&g_agg2[d * C2 + sub * 4], h.x * ex, h.y * ex, h.z * ex, h.w * ex);
    if (sub == 0) atomicAdd(&g_den2[d], ex);
}

// ---------------- finalize ----------------------------------------------------
__global__ void k_fin(float* __restrict__ out, const float* __restrict__ b2) {
    int i = blockIdx.x * blockDim.x + threadIdx.x;
    if (i < Nn * C2 / 4) {
        int node = i >> 2, cb = (i & 3) * 4;
        float inv = __frcp_rn(g_den2[node] + 1e-16f);
        float4 a = ((const float4*)g_agg2)[i];
        float4 o;
        o.x = a.x * inv + b2[cb];
        o.y = a.y * inv + b2[cb + 1];
        o.z = a.z * inv + b2[cb + 2];
        o.w = a.w * inv + b2[cb + 3];
        ((float4*)out)[i] = o;
    }
}

// ---------------- launch ------------------------------------------------------
extern "C" void kernel_launch(void* const* d_in, const int* in_sizes, int n_in,
                              void* d_out, int out_size) {
    const float* x       = (const float*)d_in[0];
    const int*   ei      = (const int*)d_in[1];   // int32 (JAX x64 disabled)
    const float* W1      = (const float*)d_in[2];
    const float* a_src1  = (const float*)d_in[3];
    const float* a_dst1  = (const float*)d_in[4];
    const float* b1      = (const float*)d_in[5];
    const float* W2      = (const float*)d_in[6];
    const float* a_src2  = (const float*)d_in[7];
    const float* a_dst2  = (const float*)d_in[8];
    const float* b2      = (const float*)d_in[9];
    float* out = (float*)d_out;

    k_init <<<(Nn * D1 / 4 + 255) / 256, 256>>>();
    k_gemm1<<<(Nn + NPB1 - 1) / NPB1, 256>>>(x, W1, a_src1, a_dst1);
    k_edge1<<<(EP * 16 + 255) / 256, 256>>>(ei);
    k_gemm2<<<(Nn + 63) / 64, 256>>>(W2, b1, a_src2, a_dst2);
    k_edge2<<<(EP * 4 + 255) / 256, 256>>>(ei);
    k_fin  <<<(Nn * C2 / 4 + 255) / 256, 256>>>(out, b2);
}

// round 8
// speedup vs baseline: 2.7172x; 1.7786x over previous
#include <cuda_runtime.h>
#include <math.h>

#define Nn 100000
#define Ee 1000000
#define EP (Ee + Nn)      // 1,100,000
#define FIN 128
#define D1 64             // HEADS*HID
#define H1 4
#define C2 16
#define SLOPE 0.2f
#define SCAN_T 512
#define NB ((Nn + SCAN_T - 1) / SCAN_T)   // 196

// ---------------- scratch ----------------------------------------------------
__device__ __align__(16) float g_h1[Nn * D1];
__device__ __align__(16) float g_as1[Nn * H1];
__device__ __align__(16) float g_ad1[Nn * H1];
__device__ __align__(16) float g_e1[Nn * D1];    // elu-normalized layer-1 out
__device__ __align__(16) float g_h2[Nn * C2];
__device__ __align__(16) float g_as2[Nn];
__device__ __align__(16) float g_ad2[Nn];

__device__ int g_rp[Nn + 1];    // CSR row pointers
__device__ int g_cur[Nn];       // counts, then cursors
__device__ int g_src[EP];       // src ids sorted by dst
__device__ int g_bsum[256];
__device__ int g_boff[256];

// ---------------- helpers ---------------------------------------------------
__device__ __forceinline__ float lrelu(float v) { return v > 0.f ? v : SLOPE * v; }

// ---------------- CSR build --------------------------------------------------
__global__ void k_zero() {
    int i = blockIdx.x * blockDim.x + threadIdx.x;
    if (i < Nn) g_cur[i] = 0;
}

__global__ void k_hist(const int* __restrict__ ei) {
    int e = blockIdx.x * blockDim.x + threadIdx.x;
    if (e >= EP) return;
    int d = (e < Ee) ? ei[e + Ee] : e - Ee;
    atomicAdd(&g_cur[d], 1);
}

__global__ void k_scan1() {
    __shared__ int sh[SCAN_T];
    int tid = threadIdx.x;
    int n = blockIdx.x * SCAN_T + tid;
    int c = (n < Nn) ? g_cur[n] : 0;
    sh[tid] = c;
    __syncthreads();
    for (int off = 1; off < SCAN_T; off <<= 1) {
        int t = (tid >= off) ? sh[tid - off] : 0;
        __syncthreads();
        sh[tid] += t;
        __syncthreads();
    }
    if (n < Nn) g_rp[n + 1] = sh[tid];
    if (tid == SCAN_T - 1) g_bsum[blockIdx.x] = sh[tid];
}

__global__ void k_scan2() {
    __shared__ int sh[256];
    int tid = threadIdx.x;
    int c = (tid < NB) ? g_bsum[tid] : 0;
    sh[tid] = c;
    __syncthreads();
    for (int off = 1; off < 256; off <<= 1) {
        int t = (tid >= off) ? sh[tid - off] : 0;
        __syncthreads();
        sh[tid] += t;
        __syncthreads();
    }
    g_boff[tid] = sh[tid] - c;   // exclusive
}

__global__ void k_scan3() {
    int n = blockIdx.x * blockDim.x + threadIdx.x;
    if (n >= Nn) return;
    int incl = g_rp[n + 1] + g_boff[n >> 9];
    g_rp[n + 1] = incl;
    int cnt = g_cur[n];
    g_cur[n] = incl - cnt;       // exclusive start -> cursor
    if (n == 0) g_rp[0] = 0;
}

__global__ void k_scatter(const int* __restrict__ ei) {
    int e = blockIdx.x * blockDim.x + threadIdx.x;
    if (e >= EP) return;
    int s, d;
    if (e < Ee) { s = ei[e]; d = ei[e + Ee]; }
    else        { s = d = e - Ee; }
    int pos = atomicAdd(&g_cur[d], 1);
    g_src[pos] = s;
}

// ---------------- layer 1 GEMM: 128 nodes/block, 4x8 per thread -------------
#define NPB1 128
__global__ void __launch_bounds__(256, 2)
k_gemm1(const float* __restrict__ x, const float* __restrict__ W1,
        const float* __restrict__ a_src1, const float* __restrict__ a_dst1) {
    extern __shared__ float dsm[];
    float* Ws = dsm;                              // [128][64]  32 KB
    float (*xs)[FIN] = (float(*)[FIN])(dsm + FIN * D1);  // [128][128] 64 KB, swizzled
    int tid = threadIdx.x;
    int base = blockIdx.x * NPB1;
    for (int i = tid; i < FIN * D1 / 4; i += 256)
        ((float4*)Ws)[i] = ((const float4*)W1)[i];
    for (int i = tid; i < NPB1 * FIN / 4; i += 256) {
        int nl = i >> 5, k4 = i & 31;
        int n = base + nl;
        float4 v = make_float4(0.f, 0.f, 0.f, 0.f);
        if (n < Nn) v = ((const float4*)(x + (size_t)n * FIN))[k4];
        ((float4*)&xs[nl][0])[k4 ^ ((nl >> 2) & 3)] = v;
    }
    __syncthreads();

    int cg = tid & 7, ng = tid >> 3;     // cols cg*8..+7, nodes ng*4..+3
    int sw = ng & 3;
    float acc[4][8];
    #pragma unroll
    for (int i = 0; i < 4; ++i)
        #pragma unroll
        for (int m = 0; m < 8; ++m) acc[i][m] = 0.f;

    #pragma unroll 2
    for (int k4 = 0; k4 < FIN / 4; ++k4) {
        float4 xq[4];
        #pragma unroll
        for (int i = 0; i < 4; ++i)
            xq[i] = ((const float4*)&xs[ng * 4 + i][0])[k4 ^ sw];
        #pragma unroll
        for (int kk = 0; kk < 4; ++kk) {
            float4 w0 = *(const float4*)&Ws[(k4 * 4 + kk) * D1 + cg * 8];
            float4 w1 = *(const float4*)&Ws[(k4 * 4 + kk) * D1 + cg * 8 + 4];
            #pragma unroll
            for (int i = 0; i < 4; ++i) {
                float xv = kk == 0 ? xq[i].x : kk == 1 ? xq[i].y : kk == 2 ? xq[i].z : xq[i].w;
                acc[i][0] += xv * w0.x; acc[i][1] += xv * w0.y;
                acc[i][2] += xv * w0.z; acc[i][3] += xv * w0.w;
                acc[i][4] += xv * w1.x; acc[i][5] += xv * w1.y;
                acc[i][6] += xv * w1.z; acc[i][7] += xv * w1.w;
            }
        }
    }

    float av[8], dv[8];
    #pragma unroll
    for (int m = 0; m < 8; ++m) { av[m] = a_src1[cg * 8 + m]; dv[m] = a_dst1[cg * 8 + m]; }
    #pragma unroll
    for (int i = 0; i < 4; ++i) {
        int n = base + ng * 4 + i;
        float sc = 0.f, dc = 0.f;
        #pragma unroll
        for (int m = 0; m < 8; ++m) { sc += acc[i][m] * av[m]; dc += acc[i][m] * dv[m]; }
        sc += __shfl_xor_sync(0xffffffffu, sc, 1);   // combine cg pair (same head)
        dc += __shfl_xor_sync(0xffffffffu, dc, 1);
        if (n < Nn) {
            *(float4*)&g_h1[n * D1 + cg * 8]     = make_float4(acc[i][0], acc[i][1], acc[i][2], acc[i][3]);
            *(float4*)&g_h1[n * D1 + cg * 8 + 4] = make_float4(acc[i][4], acc[i][5], acc[i][6], acc[i][7]);
            if (!(cg & 1)) {
                g_as1[n * H1 + (cg >> 1)] = sc;
                g_ad1[n * H1 + (cg >> 1)] = dc;
            }
        }
    }
}

// ---------------- layer 1 aggregate (CSR gather, no atomics) ----------------
// 16 threads per dst node; fused normalize + bias + ELU epilogue.
__global__ void k_agg1(const float* __restrict__ b1) {
    int tid = threadIdx.x;
    int t16 = tid & 15;
    int d = blockIdx.x * 16 + (tid >> 4);
    if (d >= Nn) return;
    int hh = t16 >> 2;
    float ad = g_ad1[d * H1 + hh];
    int j0 = g_rp[d], j1 = g_rp[d + 1];
    float4 acc = make_float4(0.f, 0.f, 0.f, 0.f);
    float dsum = 0.f;
    int sA = (j0 < j1) ? g_src[j0] : 0;
    for (int j = j0; j < j1; ++j) {
        int sN = (j + 1 < j1) ? g_src[j + 1] : 0;
        float as = g_as1[sA * H1 + hh];
        float4 h = *(const float4*)&g_h1[sA * D1 + t16 * 4];
        float ex = __expf(lrelu(as + ad));
        acc.x += h.x * ex; acc.y += h.y * ex; acc.z += h.z * ex; acc.w += h.w * ex;
        dsum += ex;
        sA = sN;
    }
    float inv = __frcp_rn(dsum + 1e-16f);
    float4 bb = *(const float4*)&b1[t16 * 4];
    float4 v;
    v.x = acc.x * inv + bb.x; v.y = acc.y * inv + bb.y;
    v.z = acc.z * inv + bb.z; v.w = acc.w * inv + bb.w;
    v.x = v.x > 0.f ? v.x : (__expf(v.x) - 1.f);
    v.y = v.y > 0.f ? v.y : (__expf(v.y) - 1.f);
    v.z = v.z > 0.f ? v.z : (__expf(v.z) - 1.f);
    v.w = v.w > 0.f ? v.w : (__expf(v.w) - 1.f);
    *(float4*)&g_e1[d * D1 + t16 * 4] = v;
}

// ---------------- layer 2 GEMM: 64 nodes/block, 4 outputs/thread ------------
#define HP 68   // padded row (17 float4s): 16B-aligned rows, conflict-free
__global__ void k_gemm2(const float* __restrict__ W2,
                        const float* __restrict__ a_src2, const float* __restrict__ a_dst2) {
    __shared__ float Ws[D1 * C2];          // 4 KB [k][c]
    __shared__ float hs[64][HP];           // 17.4 KB
    int tid = threadIdx.x;
    int base = blockIdx.x * 64;
    for (int i = tid; i < D1 * C2; i += 256) Ws[i] = W2[i];
    for (int i = tid; i < 64 * D1 / 4; i += 256) {
        int nl = i >> 4, q = i & 15;
        int n = base + nl;
        float4 v = make_float4(0.f, 0.f, 0.f, 0.f);
        if (n < Nn) v = *(const float4*)&g_e1[n * D1 + q * 4];
        *(float4*)&hs[nl][q * 4] = v;
    }
    __syncthreads();

    int nl = tid >> 2, cq = tid & 3;
    int n = base + nl;
    float4 acc = make_float4(0.f, 0.f, 0.f, 0.f);
    #pragma unroll 16
    for (int k = 0; k < D1; ++k) {
        float hv = hs[nl][k];
        float4 w = *(const float4*)&Ws[k * C2 + cq * 4];
        acc.x += hv * w.x; acc.y += hv * w.y; acc.z += hv * w.z; acc.w += hv * w.w;
    }
    float sc = acc.x * a_src2[cq * 4] + acc.y * a_src2[cq * 4 + 1]
             + acc.z * a_src2[cq * 4 + 2] + acc.w * a_src2[cq * 4 + 3];
    float dc = acc.x * a_dst2[cq * 4] + acc.y * a_dst2[cq * 4 + 1]
             + acc.z * a_dst2[cq * 4 + 2] + acc.w * a_dst2[cq * 4 + 3];
    sc += __shfl_xor_sync(0xffffffffu, sc, 1);
    sc += __shfl_xor_sync(0xffffffffu, sc, 2);
    dc += __shfl_xor_sync(0xffffffffu, dc, 1);
    dc += __shfl_xor_sync(0xffffffffu, dc, 2);
    if (n < Nn) {
        *(float4*)&g_h2[n * C2 + cq * 4] = acc;
        if (cq == 0) { g_as2[n] = sc; g_ad2[n] = dc; }
    }
}

// ---------------- layer 2 aggregate (CSR gather) + finalize -----------------
// 4 threads per dst node; writes final output directly.
__global__ void k_agg2(float* __restrict__ out, const float* __restrict__ b2) {
    int tid = threadIdx.x;
    int q = tid & 3;
    int d = blockIdx.x * 64 + (tid >> 2);
    if (d >= Nn) return;
    float ad = g_ad2[d];
    int j0 = g_rp[d], j1 = g_rp[d + 1];
    float4 acc = make_float4(0.f, 0.f, 0.f, 0.f);
    float dsum = 0.f;
    int sA = (j0 < j1) ? g_src[j0] : 0;
    for (int j = j0; j < j1; ++j) {
        int sN = (j + 1 < j1) ? g_src[j + 1] : 0;
        float as = g_as2[sA];
        float4 h = *(const float4*)&g_h2[sA * C2 + q * 4];
        float ex = __expf(lrelu(as + ad));
        acc.x += h.x * ex; acc.y += h.y * ex; acc.z += h.z * ex; acc.w += h.w * ex;
        dsum += ex;
        sA = sN;
    }
    float inv = __frcp_rn(dsum + 1e-16f);
    float4 bb = *(const float4*)&b2[q * 4];
    float4 o;
    o.x = acc.x * inv + bb.x; o.y = acc.y * inv + bb.y;
    o.z = acc.z * inv + bb.z; o.w = acc.w * inv + bb.w;
    *(float4*)&out[d * C2 + q * 4] = o;
}

// ---------------- launch ------------------------------------------------------
extern "C" void kernel_launch(void* const* d_in, const int* in_sizes, int n_in,
                              void* d_out, int out_size) {
    const float* x       = (const float*)d_in[0];
    const int*   ei      = (const int*)d_in[1];   // int32 (JAX x64 disabled)
    const float* W1      = (const float*)d_in[2];
    const float* a_src1  = (const float*)d_in[3];
    const float* a_dst1  = (const float*)d_in[4];
    const float* b1      = (const float*)d_in[5];
    const float* W2      = (const float*)d_in[6];
    const float* a_src2  = (const float*)d_in[7];
    const float* a_dst2  = (const float*)d_in[8];
    const float* b2      = (const float*)d_in[9];
    float* out = (float*)d_out;

    cudaFuncSetAttribute(k_gemm1, cudaFuncAttributeMaxDynamicSharedMemorySize, 98304);

    k_zero   <<<(Nn + 255) / 256, 256>>>();
    k_gemm1  <<<(Nn + NPB1 - 1) / NPB1, 256, 98304>>>(x, W1, a_src1, a_dst1);
    k_hist   <<<(EP + 255) / 256, 256>>>(ei);
    k_scan1  <<<NB, SCAN_T>>>();
    k_scan2  <<<1, 256>>>();
    k_scan3  <<<(Nn + 255) / 256, 256>>>();
    k_scatter<<<(EP + 255) / 256, 256>>>(ei);
    k_agg1   <<<(Nn + 15) / 16, 256>>>(b1);
    k_gemm2  <<<(Nn + 63) / 64, 256>>>(W2, a_src2, a_dst2);
    k_agg2   <<<(Nn + 63) / 64, 256>>>(out, b2);
}